// round 12
// baseline (speedup 1.0000x reference)
#include <cuda_runtime.h>
#include <cuda_bf16.h>
#include <cstdint>

#define NN 20000
#define EE 320000
#define CC 128
#define BB 20
#define RCUT 5.0f
#define EPSN 1e-8f
#define PI_F 3.14159265358979323846f

typedef unsigned long long u64;

// ---------------- scratch (static device globals; no allocation) -------------
__device__ float g_x[NN * 384];     // x = silu(q@W1+b1)@W2+b2, [N,384]
__device__ float g_dq[NN * 128];    // dq per node (written by receiver kernel)
__device__ float g_dmu[NN * 384];   // dmu per node [N,3,128]
__device__ int   g_cnt[NN];         // histogram of receiver degree
__device__ int   g_off[NN + 1];     // CSR offsets
__device__ int   g_cur[NN];         // fill cursors
__device__ int   g_csr[EE];         // edge ids sorted by receiver

__device__ __forceinline__ float silu_f(float v) {
    return v / (1.0f + __expf(-v));
}

// ---- packed fp32x2 helpers (Blackwell FFMA2 via PTX) ----
__device__ __forceinline__ u64 pack2(float lo, float hi) {
    u64 r; asm("mov.b64 %0, {%1, %2};" : "=l"(r) : "f"(lo), "f"(hi)); return r;
}
__device__ __forceinline__ void unpack2(u64 p, float& lo, float& hi) {
    asm("mov.b64 {%0, %1}, %2;" : "=f"(lo), "=f"(hi) : "l"(p));
}
__device__ __forceinline__ u64 ffma2(u64 a, u64 b, u64 c) {
    u64 d; asm("fma.rn.f32x2 %0, %1, %2, %3;" : "=l"(d) : "l"(a), "l"(b), "l"(c));
    return d;
}

// ============================================================================
// CSR build: zero -> hist -> scan -> fill
// ============================================================================
__global__ void k_zero_cnt() {
    const int i = blockIdx.x * 256 + threadIdx.x;
    if (i < NN) g_cnt[i] = 0;
}

__global__ void k_hist(const int* __restrict__ eidx) {
    const int e = blockIdx.x * 256 + threadIdx.x;
    atomicAdd(&g_cnt[eidx[e]], 1);
}

__global__ __launch_bounds__(1024) void k_scan() {
    const int t = threadIdx.x;
    const int base = t * 20;
    int local[20];
    int s = 0;
#pragma unroll
    for (int u = 0; u < 20; u++) {
        const int idx = base + u;
        const int c = (idx < NN) ? g_cnt[idx] : 0;
        local[u] = s; s += c;
    }
    __shared__ int wsum[32];
    const int lane = t & 31, w = t >> 5;
    int v = s;
#pragma unroll
    for (int d = 1; d < 32; d <<= 1) {
        const int nb = __shfl_up_sync(0xffffffffu, v, d);
        if (lane >= d) v += nb;
    }
    if (lane == 31) wsum[w] = v;
    __syncthreads();
    if (w == 0) {
        int ws = wsum[lane];
#pragma unroll
        for (int d = 1; d < 32; d <<= 1) {
            const int nb = __shfl_up_sync(0xffffffffu, ws, d);
            if (lane >= d) ws += nb;
        }
        wsum[lane] = ws;
    }
    __syncthreads();
    const int excl = (v - s) + ((w > 0) ? wsum[w - 1] : 0);
#pragma unroll
    for (int u = 0; u < 20; u++) {
        const int idx = base + u;
        if (idx < NN) {
            const int o = excl + local[u];
            g_off[idx] = o;
            g_cur[idx] = o;
        }
    }
    if (t == 1023) g_off[NN] = excl + s;   // == EE
}

__global__ void k_fill(const int* __restrict__ eidx) {
    const int e = blockIdx.x * 256 + threadIdx.x;
    const int i = eidx[e];
    const int pos = atomicAdd(&g_cur[i], 1);
    g_csr[pos] = e;
}

// ============================================================================
// K1: per-node context MLP  x = silu(q@W1+b1)@W2+b2  (zeroing removed)
// block = 128 threads, 16 nodes per block, grid = N/16 = 1250
// ============================================================================
__global__ __launch_bounds__(128) void k_node_mlp(
    const float* __restrict__ q,
    const float* __restrict__ W1, const float* __restrict__ b1,
    const float* __restrict__ W2, const float* __restrict__ b2)
{
    __shared__ float sT[128 * 16];   // transposed activations [k][n]
    const int t = threadIdx.x;
    const int n0 = blockIdx.x * 16;

    // stage qT: sT[k=t][n]
#pragma unroll
    for (int n = 0; n < 16; n++) sT[t * 16 + n] = q[(n0 + n) * 128 + t];
    __syncthreads();

    // h[n][t] = silu(b1[t] + sum_k q[n][k] * W1[k][t])
    u64 acc[8];
    {
        const float bb = __ldg(&b1[t]);
        const u64 bb2 = pack2(bb, bb);
#pragma unroll
        for (int u = 0; u < 8; u++) acc[u] = bb2;
    }
#pragma unroll 4
    for (int k = 0; k < 128; k++) {
        const float w = __ldg(&W1[k * 128 + t]);
        const u64 w2 = pack2(w, w);
        const ulonglong2* r = (const ulonglong2*)&sT[k * 16];
        const ulonglong2 a0 = r[0], a1 = r[1], a2 = r[2], a3 = r[3];
        acc[0] = ffma2(a0.x, w2, acc[0]); acc[1] = ffma2(a0.y, w2, acc[1]);
        acc[2] = ffma2(a1.x, w2, acc[2]); acc[3] = ffma2(a1.y, w2, acc[3]);
        acc[4] = ffma2(a2.x, w2, acc[4]); acc[5] = ffma2(a2.y, w2, acc[5]);
        acc[6] = ffma2(a3.x, w2, acc[6]); acc[7] = ffma2(a3.y, w2, acc[7]);
    }
    __syncthreads();
#pragma unroll
    for (int u = 0; u < 8; u++) {
        float lo, hi; unpack2(acc[u], lo, hi);
        sT[t * 16 + 2 * u]     = silu_f(lo);
        sT[t * 16 + 2 * u + 1] = silu_f(hi);
    }
    __syncthreads();

    // x[n][m] for m in {t, t+128, t+256}
    u64 y0[8], y1[8], y2[8];
    {
        const float c0 = __ldg(&b2[t]);
        const float c1 = __ldg(&b2[128 + t]);
        const float c2 = __ldg(&b2[256 + t]);
        const u64 p0 = pack2(c0, c0), p1 = pack2(c1, c1), p2 = pack2(c2, c2);
#pragma unroll
        for (int u = 0; u < 8; u++) { y0[u] = p0; y1[u] = p1; y2[u] = p2; }
    }
#pragma unroll 2
    for (int k = 0; k < 128; k++) {
        const u64 w0 = pack2(__ldg(&W2[k * 384 + t]),       __ldg(&W2[k * 384 + t]));
        const u64 w1 = pack2(__ldg(&W2[k * 384 + 128 + t]), __ldg(&W2[k * 384 + 128 + t]));
        const u64 w2 = pack2(__ldg(&W2[k * 384 + 256 + t]), __ldg(&W2[k * 384 + 256 + t]));
        const ulonglong2* r = (const ulonglong2*)&sT[k * 16];
        const ulonglong2 h0 = r[0], h1 = r[1], h2 = r[2], h3 = r[3];
        y0[0] = ffma2(h0.x, w0, y0[0]); y0[1] = ffma2(h0.y, w0, y0[1]);
        y0[2] = ffma2(h1.x, w0, y0[2]); y0[3] = ffma2(h1.y, w0, y0[3]);
        y0[4] = ffma2(h2.x, w0, y0[4]); y0[5] = ffma2(h2.y, w0, y0[5]);
        y0[6] = ffma2(h3.x, w0, y0[6]); y0[7] = ffma2(h3.y, w0, y0[7]);
        y1[0] = ffma2(h0.x, w1, y1[0]); y1[1] = ffma2(h0.y, w1, y1[1]);
        y1[2] = ffma2(h1.x, w1, y1[2]); y1[3] = ffma2(h1.y, w1, y1[3]);
        y1[4] = ffma2(h2.x, w1, y1[4]); y1[5] = ffma2(h2.y, w1, y1[5]);
        y1[6] = ffma2(h3.x, w1, y1[6]); y1[7] = ffma2(h3.y, w1, y1[7]);
        y2[0] = ffma2(h0.x, w2, y2[0]); y2[1] = ffma2(h0.y, w2, y2[1]);
        y2[2] = ffma2(h1.x, w2, y2[2]); y2[3] = ffma2(h1.y, w2, y2[3]);
        y2[4] = ffma2(h2.x, w2, y2[4]); y2[5] = ffma2(h2.y, w2, y2[5]);
        y2[6] = ffma2(h3.x, w2, y2[6]); y2[7] = ffma2(h3.y, w2, y2[7]);
    }
#pragma unroll
    for (int u = 0; u < 8; u++) {
        float a, b;
        unpack2(y0[u], a, b);
        g_x[(n0 + 2 * u) * 384 + t] = a;       g_x[(n0 + 2 * u + 1) * 384 + t] = b;
        unpack2(y1[u], a, b);
        g_x[(n0 + 2 * u) * 384 + 128 + t] = a; g_x[(n0 + 2 * u + 1) * 384 + 128 + t] = b;
        unpack2(y2[u], a, b);
        g_x[(n0 + 2 * u) * 384 + 256 + t] = a; g_x[(n0 + 2 * u + 1) * 384 + 256 + t] = b;
    }
}

// ============================================================================
// K2': receiver-driven edge accumulation — NO float atomics.
// Block = 128 threads owns 8 nodes; thread t owns channels {t,128+t,256+t}.
// Register-resident filter weights; attrs via warp shfl broadcast; 1-deep
// prefetch on the csr->e->j pointer chase. Plain STG outputs.
// grid = N/8 = 2500.
// ============================================================================
__global__ __launch_bounds__(128) void k_edge_recv(
    const int*   __restrict__ eidx,     // [2,E]
    const float* __restrict__ ew,       // [E]
    const float* __restrict__ evers,    // [E,3]
    const float* __restrict__ eattr,    // [E,B]
    const float* __restrict__ Wf,       // [B,384]
    const float* __restrict__ bf,       // [384]
    const float* __restrict__ mu)       // [N,3,128]
{
    const int t = threadIdx.x;
    const int lane = t & 31;

    // register-resident filter weights for my 3 channels
    u64 wAB[BB], wCC[BB];
#pragma unroll
    for (int b = 0; b < BB; b++) {
        const float wa = __ldg(&Wf[b * 384 + t]);
        const float wb = __ldg(&Wf[b * 384 + 128 + t]);
        const float wc = __ldg(&Wf[b * 384 + 256 + t]);
        wAB[b] = pack2(wa, wb);
        wCC[b] = pack2(wc, wc);
    }
    const u64 bAB = pack2(__ldg(&bf[t]), __ldg(&bf[128 + t]));
    const u64 bCC = pack2(__ldg(&bf[256 + t]), 0.0f);

    const int n0 = blockIdx.x * 8;
#pragma unroll 1
    for (int n = 0; n < 8; n++) {
        const int node = n0 + n;
        const int s    = __ldg(&g_off[node]);
        const int eEnd = __ldg(&g_off[node + 1]);
        float aQ = 0.0f, aX = 0.0f, aY = 0.0f, aZ = 0.0f;

        if (s < eEnd) {
            int e = __ldg(&g_csr[s]);
            int j = __ldg(&eidx[EE + e]);
#pragma unroll 1
            for (int p = s; p < eEnd; p++) {
                // prefetch next edge's pointer chase
                int e2 = 0, j2 = 0;
                if (p + 1 < eEnd) {
                    e2 = __ldg(&g_csr[p + 1]);
                    j2 = __ldg(&eidx[EE + e2]);
                }
                // gathers for current edge (issued before the filter GEMM)
                const float xA = __ldg(&g_x[j * 384 + t]);
                const float xB = __ldg(&g_x[j * 384 + 128 + t]);
                const float xC = __ldg(&g_x[j * 384 + 256 + t]);
                const float m0 = __ldg(&mu[j * 384 + t]);
                const float m1 = __ldg(&mu[j * 384 + 128 + t]);
                const float m2 = __ldg(&mu[j * 384 + 256 + t]);
                const float wgt = __ldg(&ew[e]);
                const float vx = __ldg(&evers[e * 3 + 0]);
                const float vy = __ldg(&evers[e * 3 + 1]);
                const float vz = __ldg(&evers[e * 3 + 2]);
                const float a  = (lane < BB) ? __ldg(&eattr[e * BB + lane]) : 0.0f;
                const float fc = (wgt < RCUT)
                    ? 0.5f * (cosf((PI_F / RCUT) * wgt) + 1.0f) : 0.0f;

                u64 acc = bAB, accC = bCC;
#pragma unroll
                for (int b = 0; b < BB; b++) {
                    const float ab = __shfl_sync(0xffffffffu, a, b);
                    const u64 a2 = pack2(ab, ab);
                    acc  = ffma2(wAB[b], a2, acc);
                    accC = ffma2(wCC[b], a2, accC);
                }
                float wA, wB, wC, dead;
                unpack2(acc, wA, wB);
                unpack2(accC, wC, dead);
                wA *= fc; wB *= fc; wC *= fc;

                aQ += xA * wA;
                const float dR = xB * wB;
                const float dM = xC * wC;
                aX += dR * vx + dM * m0;
                aY += dR * vy + dM * m1;
                aZ += dR * vz + dM * m2;

                e = e2; j = j2;
            }
        }
        g_dq[node * 128 + t]        = aQ;
        g_dmu[node * 384 + t]       = aX;
        g_dmu[node * 384 + 128 + t] = aY;
        g_dmu[node * 384 + 256 + t] = aZ;
    }
}

// ============================================================================
// K3: PaiNN mixing. block = 128 threads, 8 nodes per block, grid = 2500.
// ============================================================================
__global__ __launch_bounds__(128) void k_mix(
    const float* __restrict__ q,
    const float* __restrict__ mu,
    const float* __restrict__ Wmix,   // [128,256]
    const float* __restrict__ Wm1,    // [256,128]
    const float* __restrict__ bm1,    // [128]
    const float* __restrict__ Wm2,    // [128,384]
    const float* __restrict__ bm2,    // [384]
    float* __restrict__ out_q,        // [N,128]
    float* __restrict__ out_mu)       // [N,3,128]
{
    __shared__ float sMuT[128 * 24];   // [k][v*8+n]  (mun transposed)
    __shared__ float sAW[128 * 24];    // stash of mu_W per (t-channel)[v*8+n]
    __shared__ float sCtx[256 * 8];    // [k][n]
    __shared__ float sH2[128 * 8];     // [k][n]
    const int t = threadIdx.x;
    const int n0 = blockIdx.x * 8;

    float qn[8];
#pragma unroll
    for (int v = 0; v < 3; v++)
#pragma unroll
        for (int n = 0; n < 8; n++) {
            const int gi = (n0 + n) * 384 + v * 128 + t;
            sMuT[t * 24 + v * 8 + n] = mu[gi] + g_dmu[gi];
        }
#pragma unroll
    for (int n = 0; n < 8; n++)
        qn[n] = q[(n0 + n) * 128 + t] + g_dq[(n0 + n) * 128 + t];
    __syncthreads();

    // fused: mu_V and mu_W GEMMs over one sMuT pass
    u64 aV[12], aW[12];
#pragma unroll
    for (int u = 0; u < 12; u++) { aV[u] = 0ull; aW[u] = 0ull; }
#pragma unroll 2
    for (int k = 0; k < 128; k++) {
        const float wv = __ldg(&Wmix[k * 256 + t]);
        const float ww = __ldg(&Wmix[k * 256 + 128 + t]);
        const u64 wv2 = pack2(wv, wv);
        const u64 ww2 = pack2(ww, ww);
        const ulonglong2* r = (const ulonglong2*)&sMuT[k * 24];
#pragma unroll
        for (int u = 0; u < 6; u++) {
            const ulonglong2 m = r[u];
            aV[2 * u]     = ffma2(m.x, wv2, aV[2 * u]);
            aV[2 * u + 1] = ffma2(m.y, wv2, aV[2 * u + 1]);
            aW[2 * u]     = ffma2(m.x, ww2, aW[2 * u]);
            aW[2 * u + 1] = ffma2(m.y, ww2, aW[2 * u + 1]);
        }
    }
    float av[24], aw[24];
#pragma unroll
    for (int u = 0; u < 12; u++) {
        unpack2(aV[u], av[2 * u], av[2 * u + 1]);
        unpack2(aW[u], aw[2 * u], aw[2 * u + 1]);
    }

    float Vn[8], sdot[8];
#pragma unroll
    for (int n = 0; n < 8; n++) {
        Vn[n] = sqrtf(av[n] * av[n] + av[8 + n] * av[8 + n]
                      + av[16 + n] * av[16 + n] + EPSN);
        sdot[n] = av[n] * aw[n] + av[8 + n] * aw[8 + n] + av[16 + n] * aw[16 + n];
    }
#pragma unroll
    for (int u = 0; u < 24; u++) sAW[t * 24 + u] = aw[u];

#pragma unroll
    for (int n = 0; n < 8; n++) {
        sCtx[t * 8 + n] = qn[n];
        sCtx[(128 + t) * 8 + n] = Vn[n];
    }
    __syncthreads();

    u64 h[4];
    {
        const float bb = __ldg(&bm1[t]);
        const u64 bb2 = pack2(bb, bb);
#pragma unroll
        for (int u = 0; u < 4; u++) h[u] = bb2;
    }
#pragma unroll 4
    for (int k = 0; k < 256; k++) {
        const float w = __ldg(&Wm1[k * 128 + t]);
        const u64 w2 = pack2(w, w);
        const ulonglong2* r = (const ulonglong2*)&sCtx[k * 8];
        const ulonglong2 ca = r[0], cb = r[1];
        h[0] = ffma2(ca.x, w2, h[0]); h[1] = ffma2(ca.y, w2, h[1]);
        h[2] = ffma2(cb.x, w2, h[2]); h[3] = ffma2(cb.y, w2, h[3]);
    }
#pragma unroll
    for (int u = 0; u < 4; u++) {
        float lo, hi; unpack2(h[u], lo, hi);
        sH2[t * 8 + 2 * u]     = silu_f(lo);
        sH2[t * 8 + 2 * u + 1] = silu_f(hi);
    }
    __syncthreads();

    u64 ya[4], yb[4], yc[4];
    {
        const float c0 = __ldg(&bm2[t]);
        const float c1 = __ldg(&bm2[128 + t]);
        const float c2 = __ldg(&bm2[256 + t]);
        const u64 pa = pack2(c0, c0), pb = pack2(c1, c1), pc = pack2(c2, c2);
#pragma unroll
        for (int u = 0; u < 4; u++) { ya[u] = pa; yb[u] = pb; yc[u] = pc; }
    }
#pragma unroll 2
    for (int k = 0; k < 128; k++) {
        const float f0 = __ldg(&Wm2[k * 384 + t]);
        const float f1 = __ldg(&Wm2[k * 384 + 128 + t]);
        const float f2 = __ldg(&Wm2[k * 384 + 256 + t]);
        const u64 w0 = pack2(f0, f0), w1 = pack2(f1, f1), w2 = pack2(f2, f2);
        const ulonglong2* r = (const ulonglong2*)&sH2[k * 8];
        const ulonglong2 ha = r[0], hb = r[1];
        ya[0] = ffma2(ha.x, w0, ya[0]); ya[1] = ffma2(ha.y, w0, ya[1]);
        ya[2] = ffma2(hb.x, w0, ya[2]); ya[3] = ffma2(hb.y, w0, ya[3]);
        yb[0] = ffma2(ha.x, w1, yb[0]); yb[1] = ffma2(ha.y, w1, yb[1]);
        yb[2] = ffma2(hb.x, w1, yb[2]); yb[3] = ffma2(hb.y, w1, yb[3]);
        yc[0] = ffma2(ha.x, w2, yc[0]); yc[1] = ffma2(ha.y, w2, yc[1]);
        yc[2] = ffma2(hb.x, w2, yc[2]); yc[3] = ffma2(hb.y, w2, yc[3]);
    }
    float Ya[8], Yb[8], Yc[8];
#pragma unroll
    for (int u = 0; u < 4; u++) {
        unpack2(ya[u], Ya[2 * u], Ya[2 * u + 1]);
        unpack2(yb[u], Yb[2 * u], Yb[2 * u + 1]);
        unpack2(yc[u], Yc[2 * u], Yc[2 * u + 1]);
    }

#pragma unroll
    for (int n = 0; n < 8; n++) {
        out_q[(n0 + n) * 128 + t] = qn[n] + Ya[n] + Yc[n] * sdot[n];
#pragma unroll
        for (int v = 0; v < 3; v++)
            out_mu[(n0 + n) * 384 + v * 128 + t] =
                sMuT[t * 24 + v * 8 + n] + Yb[n] * sAW[t * 24 + v * 8 + n];
    }
}

// ============================================================================
extern "C" void kernel_launch(void* const* d_in, const int* in_sizes, int n_in,
                              void* d_out, int out_size)
{
    const float* q     = (const float*)d_in[0];
    const float* mu    = (const float*)d_in[1];
    const int*   eidx  = (const int*)d_in[2];
    const float* ew    = (const float*)d_in[3];
    const float* evers = (const float*)d_in[4];
    const float* eattr = (const float*)d_in[5];
    const float* Wf    = (const float*)d_in[6];
    const float* bf    = (const float*)d_in[7];
    const float* W1    = (const float*)d_in[8];
    const float* b1    = (const float*)d_in[9];
    const float* W2    = (const float*)d_in[10];
    const float* b2    = (const float*)d_in[11];
    const float* Wmix  = (const float*)d_in[12];
    const float* Wm1   = (const float*)d_in[13];
    const float* bm1   = (const float*)d_in[14];
    const float* Wm2   = (const float*)d_in[15];
    const float* bm2   = (const float*)d_in[16];

    float* out   = (float*)d_out;
    float* out_q = out;
    float* out_mu = out + (size_t)NN * 128;

    // CSR build (int atomics only)
    k_zero_cnt<<<(NN + 255) / 256, 256>>>();
    k_hist<<<EE / 256, 256>>>(eidx);
    k_scan<<<1, 1024>>>();
    k_fill<<<EE / 256, 256>>>(eidx);

    // main pipeline
    k_node_mlp<<<NN / 16, 128>>>(q, W1, b1, W2, b2);
    k_edge_recv<<<NN / 8, 128>>>(eidx, ew, evers, eattr, Wf, bf, mu);
    k_mix<<<NN / 8, 128>>>(q, mu, Wmix, Wm1, bm1, Wm2, bm2, out_q, out_mu);
}

// round 13
// speedup vs baseline: 1.0723x; 1.0723x over previous
#include <cuda_runtime.h>
#include <cuda_bf16.h>
#include <cstdint>

#define NN 20000
#define EE 320000
#define CC 128
#define BB 20
#define RCUT 5.0f
#define EPSN 1e-8f
#define PI_F 3.14159265358979323846f

typedef unsigned long long u64;

// ---------------- scratch (static device globals; no allocation) -------------
__device__ float g_x[NN * 384];       // x = silu(q@W1+b1)@W2+b2, [N,384]
__device__ float g_dq[NN * 128];      // dq per node (written by receiver kernel)
__device__ float g_dmu[NN * 384];     // dmu per node [N,3,128]
__device__ int   g_cnt[NN];           // histogram of receiver degree
__device__ int   g_off[NN + 1];       // CSR offsets
__device__ int   g_cur[NN];           // fill cursors
__device__ int   g_js[EE];            // sender j, sorted by receiver
__device__ float4 g_fcv[EE];          // (fcut, vx, vy, vz), sorted by receiver
__device__ __align__(16) float g_att[EE * BB];  // attrs, sorted by receiver

__device__ __forceinline__ float silu_f(float v) {
    return v / (1.0f + __expf(-v));
}

// ---- packed fp32x2 helpers (Blackwell FFMA2 via PTX) ----
__device__ __forceinline__ u64 pack2(float lo, float hi) {
    u64 r; asm("mov.b64 %0, {%1, %2};" : "=l"(r) : "f"(lo), "f"(hi)); return r;
}
__device__ __forceinline__ void unpack2(u64 p, float& lo, float& hi) {
    asm("mov.b64 {%0, %1}, %2;" : "=f"(lo), "=f"(hi) : "l"(p));
}
__device__ __forceinline__ u64 ffma2(u64 a, u64 b, u64 c) {
    u64 d; asm("fma.rn.f32x2 %0, %1, %2, %3;" : "=l"(d) : "l"(a), "l"(b), "l"(c));
    return d;
}

// ============================================================================
// CSR build: zero -> hist -> scan -> fill(+materialize sorted edge records)
// ============================================================================
__global__ void k_zero_cnt() {
    const int i = blockIdx.x * 256 + threadIdx.x;
    if (i < NN) g_cnt[i] = 0;
}

__global__ void k_hist(const int* __restrict__ eidx) {
    const int e = blockIdx.x * 256 + threadIdx.x;
    atomicAdd(&g_cnt[eidx[e]], 1);
}

__global__ __launch_bounds__(1024) void k_scan() {
    const int t = threadIdx.x;
    const int base = t * 20;
    int local[20];
    int s = 0;
#pragma unroll
    for (int u = 0; u < 20; u++) {
        const int idx = base + u;
        const int c = (idx < NN) ? g_cnt[idx] : 0;
        local[u] = s; s += c;
    }
    __shared__ int wsum[32];
    const int lane = t & 31, w = t >> 5;
    int v = s;
#pragma unroll
    for (int d = 1; d < 32; d <<= 1) {
        const int nb = __shfl_up_sync(0xffffffffu, v, d);
        if (lane >= d) v += nb;
    }
    if (lane == 31) wsum[w] = v;
    __syncthreads();
    if (w == 0) {
        int ws = wsum[lane];
#pragma unroll
        for (int d = 1; d < 32; d <<= 1) {
            const int nb = __shfl_up_sync(0xffffffffu, ws, d);
            if (lane >= d) ws += nb;
        }
        wsum[lane] = ws;
    }
    __syncthreads();
    const int excl = (v - s) + ((w > 0) ? wsum[w - 1] : 0);
#pragma unroll
    for (int u = 0; u < 20; u++) {
        const int idx = base + u;
        if (idx < NN) {
            const int o = excl + local[u];
            g_off[idx] = o;
            g_cur[idx] = o;
        }
    }
    if (t == 1023) g_off[NN] = excl + s;   // == EE
}

// fill + materialize: j, (fcut,versor), attrs written at CSR position
__global__ void k_fill_mat(const int* __restrict__ eidx,
                           const float* __restrict__ ew,
                           const float* __restrict__ evers,
                           const float* __restrict__ eattr) {
    const int e = blockIdx.x * 256 + threadIdx.x;
    const int i = eidx[e];
    const int j = eidx[EE + e];
    const int pos = atomicAdd(&g_cur[i], 1);
    g_js[pos] = j;
    const float wgt = __ldg(&ew[e]);
    float4 fcv;
    fcv.x = (wgt < RCUT) ? 0.5f * (cosf((PI_F / RCUT) * wgt) + 1.0f) : 0.0f;
    fcv.y = __ldg(&evers[e * 3 + 0]);
    fcv.z = __ldg(&evers[e * 3 + 1]);
    fcv.w = __ldg(&evers[e * 3 + 2]);
    g_fcv[pos] = fcv;
    const float4* src = (const float4*)&eattr[e * BB];
    float4* dst = (float4*)&g_att[pos * BB];
#pragma unroll
    for (int u = 0; u < 5; u++) dst[u] = __ldg(&src[u]);
}

// ============================================================================
// K1: per-node context MLP  x = silu(q@W1+b1)@W2+b2  (no zeroing needed)
// block = 128 threads, 16 nodes per block, grid = N/16 = 1250
// ============================================================================
__global__ __launch_bounds__(128) void k_node_mlp(
    const float* __restrict__ q,
    const float* __restrict__ W1, const float* __restrict__ b1,
    const float* __restrict__ W2, const float* __restrict__ b2)
{
    __shared__ float sT[128 * 16];   // transposed activations [k][n]
    const int t = threadIdx.x;
    const int n0 = blockIdx.x * 16;

#pragma unroll
    for (int n = 0; n < 16; n++) sT[t * 16 + n] = q[(n0 + n) * 128 + t];
    __syncthreads();

    u64 acc[8];
    {
        const float bb = __ldg(&b1[t]);
        const u64 bb2 = pack2(bb, bb);
#pragma unroll
        for (int u = 0; u < 8; u++) acc[u] = bb2;
    }
#pragma unroll 4
    for (int k = 0; k < 128; k++) {
        const float w = __ldg(&W1[k * 128 + t]);
        const u64 w2 = pack2(w, w);
        const ulonglong2* r = (const ulonglong2*)&sT[k * 16];
        const ulonglong2 a0 = r[0], a1 = r[1], a2 = r[2], a3 = r[3];
        acc[0] = ffma2(a0.x, w2, acc[0]); acc[1] = ffma2(a0.y, w2, acc[1]);
        acc[2] = ffma2(a1.x, w2, acc[2]); acc[3] = ffma2(a1.y, w2, acc[3]);
        acc[4] = ffma2(a2.x, w2, acc[4]); acc[5] = ffma2(a2.y, w2, acc[5]);
        acc[6] = ffma2(a3.x, w2, acc[6]); acc[7] = ffma2(a3.y, w2, acc[7]);
    }
    __syncthreads();
#pragma unroll
    for (int u = 0; u < 8; u++) {
        float lo, hi; unpack2(acc[u], lo, hi);
        sT[t * 16 + 2 * u]     = silu_f(lo);
        sT[t * 16 + 2 * u + 1] = silu_f(hi);
    }
    __syncthreads();

    u64 y0[8], y1[8], y2[8];
    {
        const float c0 = __ldg(&b2[t]);
        const float c1 = __ldg(&b2[128 + t]);
        const float c2 = __ldg(&b2[256 + t]);
        const u64 p0 = pack2(c0, c0), p1 = pack2(c1, c1), p2 = pack2(c2, c2);
#pragma unroll
        for (int u = 0; u < 8; u++) { y0[u] = p0; y1[u] = p1; y2[u] = p2; }
    }
#pragma unroll 2
    for (int k = 0; k < 128; k++) {
        const u64 w0 = pack2(__ldg(&W2[k * 384 + t]),       __ldg(&W2[k * 384 + t]));
        const u64 w1 = pack2(__ldg(&W2[k * 384 + 128 + t]), __ldg(&W2[k * 384 + 128 + t]));
        const u64 w2 = pack2(__ldg(&W2[k * 384 + 256 + t]), __ldg(&W2[k * 384 + 256 + t]));
        const ulonglong2* r = (const ulonglong2*)&sT[k * 16];
        const ulonglong2 h0 = r[0], h1 = r[1], h2 = r[2], h3 = r[3];
        y0[0] = ffma2(h0.x, w0, y0[0]); y0[1] = ffma2(h0.y, w0, y0[1]);
        y0[2] = ffma2(h1.x, w0, y0[2]); y0[3] = ffma2(h1.y, w0, y0[3]);
        y0[4] = ffma2(h2.x, w0, y0[4]); y0[5] = ffma2(h2.y, w0, y0[5]);
        y0[6] = ffma2(h3.x, w0, y0[6]); y0[7] = ffma2(h3.y, w0, y0[7]);
        y1[0] = ffma2(h0.x, w1, y1[0]); y1[1] = ffma2(h0.y, w1, y1[1]);
        y1[2] = ffma2(h1.x, w1, y1[2]); y1[3] = ffma2(h1.y, w1, y1[3]);
        y1[4] = ffma2(h2.x, w1, y1[4]); y1[5] = ffma2(h2.y, w1, y1[5]);
        y1[6] = ffma2(h3.x, w1, y1[6]); y1[7] = ffma2(h3.y, w1, y1[7]);
        y2[0] = ffma2(h0.x, w2, y2[0]); y2[1] = ffma2(h0.y, w2, y2[1]);
        y2[2] = ffma2(h1.x, w2, y2[2]); y2[3] = ffma2(h1.y, w2, y2[3]);
        y2[4] = ffma2(h2.x, w2, y2[4]); y2[5] = ffma2(h2.y, w2, y2[5]);
        y2[6] = ffma2(h3.x, w2, y2[6]); y2[7] = ffma2(h3.y, w2, y2[7]);
    }
#pragma unroll
    for (int u = 0; u < 8; u++) {
        float a, b;
        unpack2(y0[u], a, b);
        g_x[(n0 + 2 * u) * 384 + t] = a;       g_x[(n0 + 2 * u + 1) * 384 + t] = b;
        unpack2(y1[u], a, b);
        g_x[(n0 + 2 * u) * 384 + 128 + t] = a; g_x[(n0 + 2 * u + 1) * 384 + 128 + t] = b;
        unpack2(y2[u], a, b);
        g_x[(n0 + 2 * u) * 384 + 256 + t] = a; g_x[(n0 + 2 * u + 1) * 384 + 256 + t] = b;
    }
}

// ============================================================================
// K2: receiver-driven, streaming sorted edge records — no atomics, no chase.
// Block = 128 threads owns 2 nodes; thread t owns channels {t,128+t,256+t}.
// Per edge: 7 broadcast LDG.128 (attrs/fcv) + 6 channel gathers + 40 ffma2.
// grid = N/2 = 10000.
// ============================================================================
__global__ __launch_bounds__(128) void k_edge_recv(
    const float* __restrict__ Wf,       // [B,384]
    const float* __restrict__ bf,       // [384]
    const float* __restrict__ mu)       // [N,3,128]
{
    const int t = threadIdx.x;

    // register-resident filter weights for my 3 channels
    u64 wAB[BB], wCC[BB];
#pragma unroll
    for (int b = 0; b < BB; b++) {
        const float wa = __ldg(&Wf[b * 384 + t]);
        const float wb = __ldg(&Wf[b * 384 + 128 + t]);
        const float wc = __ldg(&Wf[b * 384 + 256 + t]);
        wAB[b] = pack2(wa, wb);
        wCC[b] = pack2(wc, wc);
    }
    const u64 bAB = pack2(__ldg(&bf[t]), __ldg(&bf[128 + t]));
    const u64 bCC = pack2(__ldg(&bf[256 + t]), 0.0f);

    const int n0 = blockIdx.x * 2;
#pragma unroll 1
    for (int n = 0; n < 2; n++) {
        const int node = n0 + n;
        const int s    = __ldg(&g_off[node]);
        const int eEnd = __ldg(&g_off[node + 1]);
        float aQ = 0.0f, aX = 0.0f, aY = 0.0f, aZ = 0.0f;

#pragma unroll 1
        for (int p = s; p < eEnd; p++) {
            const int j = __ldg(&g_js[p]);           // contiguous, L1-hot
            const float4 fcv = __ldg(&g_fcv[p]);     // contiguous, L1-hot
            const float4* ap = (const float4*)&g_att[p * BB];
            const float4 A0 = __ldg(ap + 0);
            const float4 A1 = __ldg(ap + 1);
            const float4 A2 = __ldg(ap + 2);
            const float4 A3 = __ldg(ap + 3);
            const float4 A4 = __ldg(ap + 4);

            // gathers (independent of the filter chain; issue early)
            const float xA = __ldg(&g_x[j * 384 + t]);
            const float xB = __ldg(&g_x[j * 384 + 128 + t]);
            const float xC = __ldg(&g_x[j * 384 + 256 + t]);
            const float m0 = __ldg(&mu[j * 384 + t]);
            const float m1 = __ldg(&mu[j * 384 + 128 + t]);
            const float m2 = __ldg(&mu[j * 384 + 256 + t]);

            u64 acc = bAB, accC = bCC;
#define FSTEP(bi, val) { const u64 a2 = pack2((val), (val));            \
                         acc  = ffma2(wAB[bi], a2, acc);                \
                         accC = ffma2(wCC[bi], a2, accC); }
            FSTEP(0,  A0.x) FSTEP(1,  A0.y) FSTEP(2,  A0.z) FSTEP(3,  A0.w)
            FSTEP(4,  A1.x) FSTEP(5,  A1.y) FSTEP(6,  A1.z) FSTEP(7,  A1.w)
            FSTEP(8,  A2.x) FSTEP(9,  A2.y) FSTEP(10, A2.z) FSTEP(11, A2.w)
            FSTEP(12, A3.x) FSTEP(13, A3.y) FSTEP(14, A3.z) FSTEP(15, A3.w)
            FSTEP(16, A4.x) FSTEP(17, A4.y) FSTEP(18, A4.z) FSTEP(19, A4.w)
#undef FSTEP
            float wA, wB, wC, dead;
            unpack2(acc, wA, wB);
            unpack2(accC, wC, dead);
            wA *= fcv.x; wB *= fcv.x; wC *= fcv.x;

            aQ += xA * wA;
            const float dR = xB * wB;
            const float dM = xC * wC;
            aX += dR * fcv.y + dM * m0;
            aY += dR * fcv.z + dM * m1;
            aZ += dR * fcv.w + dM * m2;
        }
        g_dq[node * 128 + t]        = aQ;
        g_dmu[node * 384 + t]       = aX;
        g_dmu[node * 384 + 128 + t] = aY;
        g_dmu[node * 384 + 256 + t] = aZ;
    }
}

// ============================================================================
// K3: PaiNN mixing. block = 128 threads, 8 nodes per block, grid = 2500.
// ============================================================================
__global__ __launch_bounds__(128) void k_mix(
    const float* __restrict__ q,
    const float* __restrict__ mu,
    const float* __restrict__ Wmix,   // [128,256]
    const float* __restrict__ Wm1,    // [256,128]
    const float* __restrict__ bm1,    // [128]
    const float* __restrict__ Wm2,    // [128,384]
    const float* __restrict__ bm2,    // [384]
    float* __restrict__ out_q,        // [N,128]
    float* __restrict__ out_mu)       // [N,3,128]
{
    __shared__ float sMuT[128 * 24];
    __shared__ float sAW[128 * 24];
    __shared__ float sCtx[256 * 8];
    __shared__ float sH2[128 * 8];
    const int t = threadIdx.x;
    const int n0 = blockIdx.x * 8;

    float qn[8];
#pragma unroll
    for (int v = 0; v < 3; v++)
#pragma unroll
        for (int n = 0; n < 8; n++) {
            const int gi = (n0 + n) * 384 + v * 128 + t;
            sMuT[t * 24 + v * 8 + n] = mu[gi] + g_dmu[gi];
        }
#pragma unroll
    for (int n = 0; n < 8; n++)
        qn[n] = q[(n0 + n) * 128 + t] + g_dq[(n0 + n) * 128 + t];
    __syncthreads();

    u64 aV[12], aW[12];
#pragma unroll
    for (int u = 0; u < 12; u++) { aV[u] = 0ull; aW[u] = 0ull; }
#pragma unroll 2
    for (int k = 0; k < 128; k++) {
        const float wv = __ldg(&Wmix[k * 256 + t]);
        const float ww = __ldg(&Wmix[k * 256 + 128 + t]);
        const u64 wv2 = pack2(wv, wv);
        const u64 ww2 = pack2(ww, ww);
        const ulonglong2* r = (const ulonglong2*)&sMuT[k * 24];
#pragma unroll
        for (int u = 0; u < 6; u++) {
            const ulonglong2 m = r[u];
            aV[2 * u]     = ffma2(m.x, wv2, aV[2 * u]);
            aV[2 * u + 1] = ffma2(m.y, wv2, aV[2 * u + 1]);
            aW[2 * u]     = ffma2(m.x, ww2, aW[2 * u]);
            aW[2 * u + 1] = ffma2(m.y, ww2, aW[2 * u + 1]);
        }
    }
    float av[24], aw[24];
#pragma unroll
    for (int u = 0; u < 12; u++) {
        unpack2(aV[u], av[2 * u], av[2 * u + 1]);
        unpack2(aW[u], aw[2 * u], aw[2 * u + 1]);
    }

    float Vn[8], sdot[8];
#pragma unroll
    for (int n = 0; n < 8; n++) {
        Vn[n] = sqrtf(av[n] * av[n] + av[8 + n] * av[8 + n]
                      + av[16 + n] * av[16 + n] + EPSN);
        sdot[n] = av[n] * aw[n] + av[8 + n] * aw[8 + n] + av[16 + n] * aw[16 + n];
    }
#pragma unroll
    for (int u = 0; u < 24; u++) sAW[t * 24 + u] = aw[u];

#pragma unroll
    for (int n = 0; n < 8; n++) {
        sCtx[t * 8 + n] = qn[n];
        sCtx[(128 + t) * 8 + n] = Vn[n];
    }
    __syncthreads();

    u64 h[4];
    {
        const float bb = __ldg(&bm1[t]);
        const u64 bb2 = pack2(bb, bb);
#pragma unroll
        for (int u = 0; u < 4; u++) h[u] = bb2;
    }
#pragma unroll 4
    for (int k = 0; k < 256; k++) {
        const float w = __ldg(&Wm1[k * 128 + t]);
        const u64 w2 = pack2(w, w);
        const ulonglong2* r = (const ulonglong2*)&sCtx[k * 8];
        const ulonglong2 ca = r[0], cb = r[1];
        h[0] = ffma2(ca.x, w2, h[0]); h[1] = ffma2(ca.y, w2, h[1]);
        h[2] = ffma2(cb.x, w2, h[2]); h[3] = ffma2(cb.y, w2, h[3]);
    }
#pragma unroll
    for (int u = 0; u < 4; u++) {
        float lo, hi; unpack2(h[u], lo, hi);
        sH2[t * 8 + 2 * u]     = silu_f(lo);
        sH2[t * 8 + 2 * u + 1] = silu_f(hi);
    }
    __syncthreads();

    u64 ya[4], yb[4], yc[4];
    {
        const float c0 = __ldg(&bm2[t]);
        const float c1 = __ldg(&bm2[128 + t]);
        const float c2 = __ldg(&bm2[256 + t]);
        const u64 pa = pack2(c0, c0), pb = pack2(c1, c1), pc = pack2(c2, c2);
#pragma unroll
        for (int u = 0; u < 4; u++) { ya[u] = pa; yb[u] = pb; yc[u] = pc; }
    }
#pragma unroll 2
    for (int k = 0; k < 128; k++) {
        const float f0 = __ldg(&Wm2[k * 384 + t]);
        const float f1 = __ldg(&Wm2[k * 384 + 128 + t]);
        const float f2 = __ldg(&Wm2[k * 384 + 256 + t]);
        const u64 w0 = pack2(f0, f0), w1 = pack2(f1, f1), w2 = pack2(f2, f2);
        const ulonglong2* r = (const ulonglong2*)&sH2[k * 8];
        const ulonglong2 ha = r[0], hb = r[1];
        ya[0] = ffma2(ha.x, w0, ya[0]); ya[1] = ffma2(ha.y, w0, ya[1]);
        ya[2] = ffma2(hb.x, w0, ya[2]); ya[3] = ffma2(hb.y, w0, ya[3]);
        yb[0] = ffma2(ha.x, w1, yb[0]); yb[1] = ffma2(ha.y, w1, yb[1]);
        yb[2] = ffma2(hb.x, w1, yb[2]); yb[3] = ffma2(hb.y, w1, yb[3]);
        yc[0] = ffma2(ha.x, w2, yc[0]); yc[1] = ffma2(ha.y, w2, yc[1]);
        yc[2] = ffma2(hb.x, w2, yc[2]); yc[3] = ffma2(hb.y, w2, yc[3]);
    }
    float Ya[8], Yb[8], Yc[8];
#pragma unroll
    for (int u = 0; u < 4; u++) {
        unpack2(ya[u], Ya[2 * u], Ya[2 * u + 1]);
        unpack2(yb[u], Yb[2 * u], Yb[2 * u + 1]);
        unpack2(yc[u], Yc[2 * u], Yc[2 * u + 1]);
    }

#pragma unroll
    for (int n = 0; n < 8; n++) {
        out_q[(n0 + n) * 128 + t] = qn[n] + Ya[n] + Yc[n] * sdot[n];
#pragma unroll
        for (int v = 0; v < 3; v++)
            out_mu[(n0 + n) * 384 + v * 128 + t] =
                sMuT[t * 24 + v * 8 + n] + Yb[n] * sAW[t * 24 + v * 8 + n];
    }
}

// ============================================================================
extern "C" void kernel_launch(void* const* d_in, const int* in_sizes, int n_in,
                              void* d_out, int out_size)
{
    const float* q     = (const float*)d_in[0];
    const float* mu    = (const float*)d_in[1];
    const int*   eidx  = (const int*)d_in[2];
    const float* ew    = (const float*)d_in[3];
    const float* evers = (const float*)d_in[4];
    const float* eattr = (const float*)d_in[5];
    const float* Wf    = (const float*)d_in[6];
    const float* bf    = (const float*)d_in[7];
    const float* W1    = (const float*)d_in[8];
    const float* b1    = (const float*)d_in[9];
    const float* W2    = (const float*)d_in[10];
    const float* b2    = (const float*)d_in[11];
    const float* Wmix  = (const float*)d_in[12];
    const float* Wm1   = (const float*)d_in[13];
    const float* bm1   = (const float*)d_in[14];
    const float* Wm2   = (const float*)d_in[15];
    const float* bm2   = (const float*)d_in[16];

    float* out   = (float*)d_out;
    float* out_q = out;
    float* out_mu = out + (size_t)NN * 128;

    // CSR build + edge-record materialization (int atomics only)
    k_zero_cnt<<<(NN + 255) / 256, 256>>>();
    k_hist<<<EE / 256, 256>>>(eidx);
    k_scan<<<1, 1024>>>();
    k_fill_mat<<<EE / 256, 256>>>(eidx, ew, evers, eattr);

    // main pipeline
    k_node_mlp<<<NN / 16, 128>>>(q, W1, b1, W2, b2);
    k_edge_recv<<<NN / 2, 128>>>(Wf, bf, mu);
    k_mix<<<NN / 8, 128>>>(q, mu, Wmix, Wm1, bm1, Wm2, bm2, out_q, out_mu);
}

// round 14
// speedup vs baseline: 1.2527x; 1.1683x over previous
#include <cuda_runtime.h>
#include <cuda_bf16.h>
#include <cstdint>

#define NN 20000
#define EE 320000
#define CC 128
#define BB 20
#define RCUT 5.0f
#define EPSN 1e-8f
#define PI_F 3.14159265358979323846f

typedef unsigned long long u64;

// ---------------- scratch (static device globals; no allocation) -------------
__device__ float g_x[NN * 384];     // x = silu(q@W1+b1)@W2+b2, [N,384]
__device__ float g_dq[NN * 128];    // scatter accum dq
__device__ float g_dmu[NN * 384];   // scatter accum dmu [N,3,128]

__device__ __forceinline__ float silu_f(float v) {
    return v / (1.0f + __expf(-v));
}

// ---- packed fp32x2 helpers (Blackwell FFMA2 via PTX) ----
__device__ __forceinline__ u64 pack2(float lo, float hi) {
    u64 r; asm("mov.b64 %0, {%1, %2};" : "=l"(r) : "f"(lo), "f"(hi)); return r;
}
__device__ __forceinline__ void unpack2(u64 p, float& lo, float& hi) {
    asm("mov.b64 {%0, %1}, %2;" : "=f"(lo), "=f"(hi) : "l"(p));
}
__device__ __forceinline__ u64 ffma2(u64 a, u64 b, u64 c) {
    u64 d; asm("fma.rn.f32x2 %0, %1, %2, %3;" : "=l"(d) : "l"(a), "l"(b), "l"(c));
    return d;
}

__device__ __forceinline__ void red_add_v4(float* ptr, float4 v) {
    asm volatile("red.global.add.v4.f32 [%0], {%1, %2, %3, %4};"
                 :: "l"(ptr), "f"(v.x), "f"(v.y), "f"(v.z), "f"(v.w)
                 : "memory");
}

// ============================================================================
// K1: per-node context MLP  x = silu(q@W1+b1)@W2+b2   (+ zero dq/dmu accums)
// 128 threads, 16 nodes/block, grid = 1250. Weight slabs staged via smem.
// ============================================================================
__global__ __launch_bounds__(128) void k_node_mlp(
    const float* __restrict__ q,
    const float* __restrict__ W1, const float* __restrict__ b1,
    const float* __restrict__ W2, const float* __restrict__ b2)
{
    __shared__ float sT[128 * 16];   // 8 KB — transposed activations [k][n]
    __shared__ float sW[2048];       // 8 KB — weight tile
    const int t = threadIdx.x;
    const int n0 = blockIdx.x * 16;

    // zero the scatter accumulators for this node range (before K2 runs)
#pragma unroll
    for (int n = 0; n < 16; n++) {
        g_dq[(n0 + n) * 128 + t] = 0.0f;
        g_dmu[(n0 + n) * 384 + t] = 0.0f;
        g_dmu[(n0 + n) * 384 + 128 + t] = 0.0f;
        g_dmu[(n0 + n) * 384 + 256 + t] = 0.0f;
    }

    // stage qT: sT[k=t][n]
#pragma unroll
    for (int n = 0; n < 16; n++) sT[t * 16 + n] = q[(n0 + n) * 128 + t];
    __syncthreads();

    // ---- layer 1: h[n][t] = silu(b1[t] + sum_k q[n][k]*W1[k][t]) ----
    u64 acc[8];
    {
        const float bb = __ldg(&b1[t]);
        const u64 bb2 = pack2(bb, bb);
#pragma unroll
        for (int u = 0; u < 8; u++) acc[u] = bb2;
    }
    for (int k0 = 0; k0 < 128; k0 += 16) {           // tile: 16 x 128 = 8 KB
        const float4* src = (const float4*)&W1[k0 * 128];
#pragma unroll
        for (int i = 0; i < 4; i++)
            ((float4*)sW)[t + 128 * i] = __ldg(&src[t + 128 * i]);
        __syncthreads();
#pragma unroll 8
        for (int kk = 0; kk < 16; kk++) {
            const float w = sW[kk * 128 + t];
            const u64 w2 = pack2(w, w);
            const ulonglong2* r = (const ulonglong2*)&sT[(k0 + kk) * 16];
            const ulonglong2 a0 = r[0], a1 = r[1], a2 = r[2], a3 = r[3];
            acc[0] = ffma2(a0.x, w2, acc[0]); acc[1] = ffma2(a0.y, w2, acc[1]);
            acc[2] = ffma2(a1.x, w2, acc[2]); acc[3] = ffma2(a1.y, w2, acc[3]);
            acc[4] = ffma2(a2.x, w2, acc[4]); acc[5] = ffma2(a2.y, w2, acc[5]);
            acc[6] = ffma2(a3.x, w2, acc[6]); acc[7] = ffma2(a3.y, w2, acc[7]);
        }
        __syncthreads();
    }
#pragma unroll
    for (int u = 0; u < 8; u++) {
        float lo, hi; unpack2(acc[u], lo, hi);
        sT[t * 16 + 2 * u]     = silu_f(lo);
        sT[t * 16 + 2 * u + 1] = silu_f(hi);
    }
    __syncthreads();

    // ---- layer 2: x[n][m], m in {t, t+128, t+256} ----
    u64 y0[8], y1[8], y2[8];
    {
        const float c0 = __ldg(&b2[t]);
        const float c1 = __ldg(&b2[128 + t]);
        const float c2 = __ldg(&b2[256 + t]);
        const u64 p0 = pack2(c0, c0), p1 = pack2(c1, c1), p2 = pack2(c2, c2);
#pragma unroll
        for (int u = 0; u < 8; u++) { y0[u] = p0; y1[u] = p1; y2[u] = p2; }
    }
    for (int k0 = 0; k0 < 128; k0 += 4) {            // tile: 4 x 384 = 6 KB
        const float4* src = (const float4*)&W2[k0 * 384];
#pragma unroll
        for (int i = 0; i < 3; i++)
            ((float4*)sW)[t + 128 * i] = __ldg(&src[t + 128 * i]);
        __syncthreads();
#pragma unroll
        for (int kk = 0; kk < 4; kk++) {
            const float f0 = sW[kk * 384 + t];
            const float f1 = sW[kk * 384 + 128 + t];
            const float f2 = sW[kk * 384 + 256 + t];
            const u64 w0 = pack2(f0, f0), w1 = pack2(f1, f1), w2 = pack2(f2, f2);
            const ulonglong2* r = (const ulonglong2*)&sT[(k0 + kk) * 16];
            const ulonglong2 h0 = r[0], h1 = r[1], h2 = r[2], h3 = r[3];
            y0[0] = ffma2(h0.x, w0, y0[0]); y0[1] = ffma2(h0.y, w0, y0[1]);
            y0[2] = ffma2(h1.x, w0, y0[2]); y0[3] = ffma2(h1.y, w0, y0[3]);
            y0[4] = ffma2(h2.x, w0, y0[4]); y0[5] = ffma2(h2.y, w0, y0[5]);
            y0[6] = ffma2(h3.x, w0, y0[6]); y0[7] = ffma2(h3.y, w0, y0[7]);
            y1[0] = ffma2(h0.x, w1, y1[0]); y1[1] = ffma2(h0.y, w1, y1[1]);
            y1[2] = ffma2(h1.x, w1, y1[2]); y1[3] = ffma2(h1.y, w1, y1[3]);
            y1[4] = ffma2(h2.x, w1, y1[4]); y1[5] = ffma2(h2.y, w1, y1[5]);
            y1[6] = ffma2(h3.x, w1, y1[6]); y1[7] = ffma2(h3.y, w1, y1[7]);
            y2[0] = ffma2(h0.x, w2, y2[0]); y2[1] = ffma2(h0.y, w2, y2[1]);
            y2[2] = ffma2(h1.x, w2, y2[2]); y2[3] = ffma2(h1.y, w2, y2[3]);
            y2[4] = ffma2(h2.x, w2, y2[4]); y2[5] = ffma2(h2.y, w2, y2[5]);
            y2[6] = ffma2(h3.x, w2, y2[6]); y2[7] = ffma2(h3.y, w2, y2[7]);
        }
        __syncthreads();
    }
#pragma unroll
    for (int u = 0; u < 8; u++) {
        float a, b;
        unpack2(y0[u], a, b);
        g_x[(n0 + 2 * u) * 384 + t] = a;       g_x[(n0 + 2 * u + 1) * 384 + t] = b;
        unpack2(y1[u], a, b);
        g_x[(n0 + 2 * u) * 384 + 128 + t] = a; g_x[(n0 + 2 * u + 1) * 384 + 128 + t] = b;
        unpack2(y2[u], a, b);
        g_x[(n0 + 2 * u) * 384 + 256 + t] = a; g_x[(n0 + 2 * u + 1) * 384 + 256 + t] = b;
    }
}

// ============================================================================
// K2: edge messages (R11 verbatim — best measured form).
// TE=32 edges per block; grid = E/TE = 10000.
// ============================================================================
#define TE 32
__global__ __launch_bounds__(128) void k_edge(
    const int*   __restrict__ eidx,     // [2,E]
    const float* __restrict__ ew,       // [E]
    const float* __restrict__ evers,    // [E,3]
    const float* __restrict__ eattr,    // [E,B]
    const float* __restrict__ Wf,       // [B,384]
    const float* __restrict__ bf,       // [384]
    const float* __restrict__ mu)       // [N,3,128]
{
    __shared__ u64   sA2[BB * TE];
    __shared__ float sFc[TE];
    __shared__ float sV[3 * TE];
    __shared__ int   sIJ[2 * TE];
    __shared__ float sSt[4][2][4][32];    // [warp][buf][row][chan]

    const int t = threadIdx.x;
    const int w = t >> 5;
    const int l = t & 31;
    const int e0 = blockIdx.x * TE;

    for (int idx = t; idx < TE * BB; idx += 128) {
        const int e = idx / BB, b = idx % BB;
        const float a = __ldg(&eattr[(e0 + e) * BB + b]);
        sA2[b * TE + e] = pack2(a, a);
    }
    if (t < TE) {
        const int e = e0 + t;
        sIJ[t]      = eidx[e];
        sIJ[TE + t] = eidx[EE + e];
        const float wgt = __ldg(&ew[e]);
        sFc[t] = (wgt < RCUT) ? 0.5f * (cosf((PI_F / RCUT) * wgt) + 1.0f) : 0.0f;
        sV[t]          = __ldg(&evers[e * 3 + 0]);
        sV[TE + t]     = __ldg(&evers[e * 3 + 1]);
        sV[2 * TE + t] = __ldg(&evers[e * 3 + 2]);
    }

    u64 wAB[BB], wCC[BB];
#pragma unroll
    for (int b = 0; b < BB; b++) {
        const float wa = __ldg(&Wf[b * 384 + t]);
        const float wb = __ldg(&Wf[b * 384 + 128 + t]);
        const float wc = __ldg(&Wf[b * 384 + 256 + t]);
        wAB[b] = pack2(wa, wb);
        wCC[b] = pack2(wc, wc);
    }
    const u64 bAB = pack2(__ldg(&bf[t]), __ldg(&bf[128 + t]));
    const u64 bCC = pack2(__ldg(&bf[256 + t]), 0.0f);
    __syncthreads();

    const int rr = l >> 3;
    const int cq = w * 32 + (l & 7) * 4;

    for (int e = 0; e < TE; e++) {
        const int i = sIJ[e];
        const int j = sIJ[TE + e];
        const float fc = sFc[e];
        const float vx = sV[e], vy = sV[TE + e], vz = sV[2 * TE + e];

        u64 acc = bAB, accC = bCC;
#pragma unroll
        for (int b = 0; b < BB; b++) {
            const u64 a2 = sA2[b * TE + e];
            acc  = ffma2(wAB[b], a2, acc);
            accC = ffma2(wCC[b], a2, accC);
        }
        float wijA, wijB, wijC, dead;
        unpack2(acc, wijA, wijB);
        unpack2(accC, wijC, dead);
        wijA *= fc; wijB *= fc; wijC *= fc;

        const float xA = __ldg(&g_x[j * 384 + t]);
        const float xB = __ldg(&g_x[j * 384 + 128 + t]);
        const float xC = __ldg(&g_x[j * 384 + 256 + t]);
        const float m0 = __ldg(&mu[j * 384 + t]);
        const float m1 = __ldg(&mu[j * 384 + 128 + t]);
        const float m2 = __ldg(&mu[j * 384 + 256 + t]);

        const float dq = xA * wijA;
        const float dR = xB * wijB;
        const float dM = xC * wijC;

        const int buf = e & 1;
        sSt[w][buf][0][l] = dq;
        sSt[w][buf][1][l] = dR * vx + dM * m0;
        sSt[w][buf][2][l] = dR * vy + dM * m1;
        sSt[w][buf][3][l] = dR * vz + dM * m2;
        __syncwarp();

        const float4 v = *(const float4*)&sSt[w][buf][rr][(l & 7) * 4];
        float* base = (rr == 0) ? &g_dq[i * 128 + cq]
                                : &g_dmu[i * 384 + (rr - 1) * 128 + cq];
        red_add_v4(base, v);
    }
}

// ============================================================================
// K3: PaiNN mixing. 128 threads, 8 nodes/block, grid = 2500.
// Weight slabs for all three GEMM loops staged via a shared 12 KB scratch.
// ============================================================================
__global__ __launch_bounds__(128) void k_mix(
    const float* __restrict__ q,
    const float* __restrict__ mu,
    const float* __restrict__ Wmix,   // [128,256]
    const float* __restrict__ Wm1,    // [256,128]
    const float* __restrict__ bm1,    // [128]
    const float* __restrict__ Wm2,    // [128,384]
    const float* __restrict__ bm2,    // [384]
    float* __restrict__ out_q,        // [N,128]
    float* __restrict__ out_mu)       // [N,3,128]
{
    __shared__ float smem[11264];            // 44 KB total, manual layout
    float* sMuT = smem;                      // [128][24]  12 KB
    float* sAW  = smem + 3072;               // [128][24]  12 KB
    float* sCtx = smem + 6144;               // [256][8]    8 KB
    float* sH2  = smem + 8192;               // [128][8]    4 KB
    float* sW   = smem + 9216;               // 2048 floats 8 KB scratch

    const int t = threadIdx.x;
    const int n0 = blockIdx.x * 8;

    float qn[8];
#pragma unroll
    for (int v = 0; v < 3; v++)
#pragma unroll
        for (int n = 0; n < 8; n++) {
            const int gi = (n0 + n) * 384 + v * 128 + t;
            sMuT[t * 24 + v * 8 + n] = mu[gi] + g_dmu[gi];
        }
#pragma unroll
    for (int n = 0; n < 8; n++)
        qn[n] = q[(n0 + n) * 128 + t] + g_dq[(n0 + n) * 128 + t];
    __syncthreads();

    // ---- fused mu_V / mu_W GEMMs, Wmix staged 8 k at a time (8 KB) ----
    u64 aV[12], aW[12];
#pragma unroll
    for (int u = 0; u < 12; u++) { aV[u] = 0ull; aW[u] = 0ull; }
    for (int k0 = 0; k0 < 128; k0 += 8) {
        const float4* src = (const float4*)&Wmix[k0 * 256];
#pragma unroll
        for (int i = 0; i < 4; i++)
            ((float4*)sW)[t + 128 * i] = __ldg(&src[t + 128 * i]);
        __syncthreads();
#pragma unroll
        for (int kk = 0; kk < 8; kk++) {
            const float wv = sW[kk * 256 + t];
            const float ww = sW[kk * 256 + 128 + t];
            const u64 wv2 = pack2(wv, wv);
            const u64 ww2 = pack2(ww, ww);
            const ulonglong2* r = (const ulonglong2*)&sMuT[(k0 + kk) * 24];
#pragma unroll
            for (int u = 0; u < 6; u++) {
                const ulonglong2 m = r[u];
                aV[2 * u]     = ffma2(m.x, wv2, aV[2 * u]);
                aV[2 * u + 1] = ffma2(m.y, wv2, aV[2 * u + 1]);
                aW[2 * u]     = ffma2(m.x, ww2, aW[2 * u]);
                aW[2 * u + 1] = ffma2(m.y, ww2, aW[2 * u + 1]);
            }
        }
        __syncthreads();
    }
    float av[24], aw[24];
#pragma unroll
    for (int u = 0; u < 12; u++) {
        unpack2(aV[u], av[2 * u], av[2 * u + 1]);
        unpack2(aW[u], aw[2 * u], aw[2 * u + 1]);
    }

    float Vn[8], sdot[8];
#pragma unroll
    for (int n = 0; n < 8; n++) {
        Vn[n] = sqrtf(av[n] * av[n] + av[8 + n] * av[8 + n]
                      + av[16 + n] * av[16 + n] + EPSN);
        sdot[n] = av[n] * aw[n] + av[8 + n] * aw[8 + n] + av[16 + n] * aw[16 + n];
    }
#pragma unroll
    for (int u = 0; u < 24; u++) sAW[t * 24 + u] = aw[u];

#pragma unroll
    for (int n = 0; n < 8; n++) {
        sCtx[t * 8 + n] = qn[n];
        sCtx[(128 + t) * 8 + n] = Vn[n];
    }
    __syncthreads();

    // ---- MLP layer 1: Wm1 staged 16 k at a time (8 KB) ----
    u64 h[4];
    {
        const float bb = __ldg(&bm1[t]);
        const u64 bb2 = pack2(bb, bb);
#pragma unroll
        for (int u = 0; u < 4; u++) h[u] = bb2;
    }
    for (int k0 = 0; k0 < 256; k0 += 16) {
        const float4* src = (const float4*)&Wm1[k0 * 128];
#pragma unroll
        for (int i = 0; i < 4; i++)
            ((float4*)sW)[t + 128 * i] = __ldg(&src[t + 128 * i]);
        __syncthreads();
#pragma unroll 8
        for (int kk = 0; kk < 16; kk++) {
            const float w = sW[kk * 128 + t];
            const u64 w2 = pack2(w, w);
            const ulonglong2* r = (const ulonglong2*)&sCtx[(k0 + kk) * 8];
            const ulonglong2 ca = r[0], cb = r[1];
            h[0] = ffma2(ca.x, w2, h[0]); h[1] = ffma2(ca.y, w2, h[1]);
            h[2] = ffma2(cb.x, w2, h[2]); h[3] = ffma2(cb.y, w2, h[3]);
        }
        __syncthreads();
    }
#pragma unroll
    for (int u = 0; u < 4; u++) {
        float lo, hi; unpack2(h[u], lo, hi);
        sH2[t * 8 + 2 * u]     = silu_f(lo);
        sH2[t * 8 + 2 * u + 1] = silu_f(hi);
    }
    __syncthreads();

    // ---- MLP layer 2: Wm2 staged 4 k at a time (6 KB) ----
    u64 ya[4], yb[4], yc[4];
    {
        const float c0 = __ldg(&bm2[t]);
        const float c1 = __ldg(&bm2[128 + t]);
        const float c2 = __ldg(&bm2[256 + t]);
        const u64 pa = pack2(c0, c0), pb = pack2(c1, c1), pc = pack2(c2, c2);
#pragma unroll
        for (int u = 0; u < 4; u++) { ya[u] = pa; yb[u] = pb; yc[u] = pc; }
    }
    for (int k0 = 0; k0 < 128; k0 += 4) {
        const float4* src = (const float4*)&Wm2[k0 * 384];
#pragma unroll
        for (int i = 0; i < 3; i++)
            ((float4*)sW)[t + 128 * i] = __ldg(&src[t + 128 * i]);
        __syncthreads();
#pragma unroll
        for (int kk = 0; kk < 4; kk++) {
            const float f0 = sW[kk * 384 + t];
            const float f1 = sW[kk * 384 + 128 + t];
            const float f2 = sW[kk * 384 + 256 + t];
            const u64 w0 = pack2(f0, f0), w1 = pack2(f1, f1), w2 = pack2(f2, f2);
            const ulonglong2* r = (const ulonglong2*)&sH2[(k0 + kk) * 8];
            const ulonglong2 ha = r[0], hb = r[1];
            ya[0] = ffma2(ha.x, w0, ya[0]); ya[1] = ffma2(ha.y, w0, ya[1]);
            ya[2] = ffma2(hb.x, w0, ya[2]); ya[3] = ffma2(hb.y, w0, ya[3]);
            yb[0] = ffma2(ha.x, w1, yb[0]); yb[1] = ffma2(ha.y, w1, yb[1]);
            yb[2] = ffma2(hb.x, w1, yb[2]); yb[3] = ffma2(hb.y, w1, yb[3]);
            yc[0] = ffma2(ha.x, w2, yc[0]); yc[1] = ffma2(ha.y, w2, yc[1]);
            yc[2] = ffma2(hb.x, w2, yc[2]); yc[3] = ffma2(hb.y, w2, yc[3]);
        }
        __syncthreads();
    }
    float Ya[8], Yb[8], Yc[8];
#pragma unroll
    for (int u = 0; u < 4; u++) {
        unpack2(ya[u], Ya[2 * u], Ya[2 * u + 1]);
        unpack2(yb[u], Yb[2 * u], Yb[2 * u + 1]);
        unpack2(yc[u], Yc[2 * u], Yc[2 * u + 1]);
    }

#pragma unroll
    for (int n = 0; n < 8; n++) {
        out_q[(n0 + n) * 128 + t] = qn[n] + Ya[n] + Yc[n] * sdot[n];
#pragma unroll
        for (int v = 0; v < 3; v++)
            out_mu[(n0 + n) * 384 + v * 128 + t] =
                sMuT[t * 24 + v * 8 + n] + Yb[n] * sAW[t * 24 + v * 8 + n];
    }
}

// ============================================================================
extern "C" void kernel_launch(void* const* d_in, const int* in_sizes, int n_in,
                              void* d_out, int out_size)
{
    const float* q     = (const float*)d_in[0];
    const float* mu    = (const float*)d_in[1];
    const int*   eidx  = (const int*)d_in[2];
    const float* ew    = (const float*)d_in[3];
    const float* evers = (const float*)d_in[4];
    const float* eattr = (const float*)d_in[5];
    const float* Wf    = (const float*)d_in[6];
    const float* bf    = (const float*)d_in[7];
    const float* W1    = (const float*)d_in[8];
    const float* b1    = (const float*)d_in[9];
    const float* W2    = (const float*)d_in[10];
    const float* b2    = (const float*)d_in[11];
    const float* Wmix  = (const float*)d_in[12];
    const float* Wm1   = (const float*)d_in[13];
    const float* bm1   = (const float*)d_in[14];
    const float* Wm2   = (const float*)d_in[15];
    const float* bm2   = (const float*)d_in[16];

    float* out   = (float*)d_out;
    float* out_q = out;
    float* out_mu = out + (size_t)NN * 128;

    k_node_mlp<<<NN / 16, 128>>>(q, W1, b1, W2, b2);
    k_edge<<<EE / TE, 128>>>(eidx, ew, evers, eattr, Wf, bf, mu);
    k_mix<<<NN / 8, 128>>>(q, mu, Wmix, Wm1, bm1, Wm2, bm2, out_q, out_mu);
}